// round 6
// baseline (speedup 1.0000x reference)
#include <cuda_runtime.h>
#include <math.h>
#include <cstdint>

#define B_   16
#define N_   1024
#define E_   768
#define H_   12
#define D_   64
#define TOK  (B_ * N_)

// Scratch. Q,K: [b*H+h][n][d], d interleaved in 8-groups (pos2q=k_q, pos2q+1=k_{q+4}),
// Q pre-scaled 0.125. V plain. AO: [b][n][e] interleaved. Xr/Wr: rounded+interleaved.
__device__ float g_Q [(size_t)B_ * H_ * N_ * D_];
__device__ float g_K [(size_t)B_ * H_ * N_ * D_];
__device__ float g_V [(size_t)B_ * H_ * N_ * D_];
__device__ float g_AO[(size_t)TOK * E_];
__device__ float g_Xr[(size_t)TOK * E_];
__device__ float g_Wr[4][(size_t)E_ * E_];

// ---------------------------------------------------------------------------
__device__ __forceinline__ uint32_t smem_u32(const void* p) {
    uint32_t a;
    asm("{ .reg .u64 t; cvta.to.shared.u64 t, %1; cvt.u32.u64 %0, t; }" : "=r"(a) : "l"(p));
    return a;
}
__device__ __forceinline__ uint32_t tf32b(float x) {
    uint32_t u;
    asm("cvt.rna.tf32.f32 %0, %1;" : "=r"(u) : "f"(x));
    return u;
}
__device__ __forceinline__ float u2f(uint32_t u) { return __uint_as_float(u); }
__device__ __forceinline__ uint32_t f2u(float f) { return __float_as_uint(f); }

__device__ __forceinline__ void mma8(float* c, const uint32_t* a,
                                     uint32_t b0, uint32_t b1) {
    asm volatile(
        "mma.sync.aligned.m16n8k8.row.col.f32.tf32.tf32.f32 "
        "{%0,%1,%2,%3}, {%4,%5,%6,%7}, {%8,%9}, {%0,%1,%2,%3};\n"
        : "+f"(c[0]), "+f"(c[1]), "+f"(c[2]), "+f"(c[3])
        : "r"(a[0]), "r"(a[1]), "r"(a[2]), "r"(a[3]), "r"(b0), "r"(b1));
}

#define CP16(dst, src) \
    asm volatile("cp.async.cg.shared.global [%0], [%1], 16;" :: "r"(dst), "l"(src))
#define CP_COMMIT() asm volatile("cp.async.commit_group;" ::: "memory")
template <int N>
__device__ __forceinline__ void cp_wait() {
    asm volatile("cp.async.wait_group %0;" :: "n"(N) : "memory");
}

// Fast exp on the FMA pipe (no MUFU).
__device__ __forceinline__ float fexp(float x) {
    x = fmaxf(x, -80.0f);
    float t = x * 1.4426950408889634f;
    float z = t + 12582912.0f;
    int   e = __float_as_int(z);
    float f = t - (z - 12582912.0f);
    float p = 1.3333558e-3f;
    p = fmaf(p, f, 9.6181291e-3f);
    p = fmaf(p, f, 5.5504109e-2f);
    p = fmaf(p, f, 2.4022651e-1f);
    p = fmaf(p, f, 6.9314718e-1f);
    p = fmaf(p, f, 1.0f);
    return __int_as_float(__float_as_int(p) + (e << 23));
}

// ---------------------------------------------------------------------------
// Prepass: tf32 RN round + interleave k within 8-groups.
// positions: {k0,k4,k1,k5,k2,k6,k3,k7}
// ---------------------------------------------------------------------------
__global__ __launch_bounds__(256) void prep8_kernel(
    const float4* __restrict__ in, float4* __restrict__ out, int n8)
{
    int i = blockIdx.x * blockDim.x + threadIdx.x;
    if (i >= n8) return;
    float4 a = in[2 * i], b = in[2 * i + 1];
    float4 o1 = make_float4(u2f(tf32b(a.x)), u2f(tf32b(b.x)),
                            u2f(tf32b(a.y)), u2f(tf32b(b.y)));
    float4 o2 = make_float4(u2f(tf32b(a.z)), u2f(tf32b(b.z)),
                            u2f(tf32b(a.w)), u2f(tf32b(b.w)));
    out[2 * i] = o1; out[2 * i + 1] = o2;
}

// ---------------------------------------------------------------------------
// tf32 mma.sync GEMM, cp.async 3-stage, group-XOR swizzle (stride 32, no pad).
// 256 thr (8 warps, 4x2), CTA 128x128x32, warp 32x64. All frag loads LDS.64.
// QKV=true: grid.y=18, which: 0=Q (interleave + x0.125), 1=K (interleave), 2=V plain.
// ---------------------------------------------------------------------------
#define GSTG 8192                            // floats/stage (A 4096 + B 4096)
#define GEMM_SMEM (3 * GSTG * 4)             // 98304 B

template <bool QKV>
__global__ __launch_bounds__(256, 2) void tf32_gemm(
    const float* __restrict__ A, const float* __restrict__ Wbase,
    const float* __restrict__ bp0, const float* __restrict__ bp1,
    const float* __restrict__ bp2,
    float* __restrict__ C0, float* __restrict__ C1, float* __restrict__ C2)
{
    extern __shared__ float sm[];
    const uint32_t sb = smem_u32(sm);
    const int tid = threadIdx.x;
    const int wid = tid >> 5, lane = tid & 31;
    const int g = lane >> 2, q = lane & 3;
    const int wm = wid >> 1, wn = wid & 1;
    const int m0 = blockIdx.x * 128;

    int n0, which = 0;
    const float* W;
    const float* bias;
    float* C;
    if (QKV) {
        which = blockIdx.y / 6;
        n0 = (blockIdx.y % 6) * 128;
        W = Wbase + (size_t)which * E_ * E_;
        bias = (which == 0) ? bp0 : (which == 1) ? bp1 : bp2;
        C = (which == 0) ? C0 : (which == 1) ? C1 : C2;
    } else {
        n0 = blockIdx.y * 128;
        W = Wbase; bias = bp0; C = C0;
    }

    auto issue = [&](int ko) {
        uint32_t base = sb + (uint32_t)(ko % 3) * GSTG * 4;
        const float* Ab = A + (size_t)m0 * E_ + ko * 32;
        const float* Wb = W + (size_t)n0 * E_ + ko * 32;
#pragma unroll
        for (int i = 0; i < 4; i++) {
            int c = tid + i * 256;          // 0..1023
            int row = c >> 3, c4 = c & 7;
            uint32_t off = (uint32_t)(row * 32 + (c4 ^ ((row & 3) << 1)) * 4) * 4;
            CP16(base + off, Ab + (size_t)row * E_ + c4 * 4);
            CP16(base + 4096 * 4 + off, Wb + (size_t)row * E_ + c4 * 4);
        }
    };

    float acc[2][8][4];
#pragma unroll
    for (int mi = 0; mi < 2; mi++)
#pragma unroll
        for (int ni = 0; ni < 8; ni++)
#pragma unroll
            for (int r = 0; r < 4; r++) acc[mi][ni][r] = 0.0f;

    issue(0); CP_COMMIT();
    issue(1); CP_COMMIT();

    for (int ko = 0; ko < E_ / 32; ko++) {
        if (ko + 2 < E_ / 32) issue(ko + 2);
        CP_COMMIT();
        cp_wait<2>();
        __syncthreads();
        const float* pa = sm + (ko % 3) * GSTG;
        const float* pb = pa + 4096;
#pragma unroll
        for (int kc = 0; kc < 4; kc++) {
            const int ch = (kc ^ (g & 3)) * 8 + 2 * q;
            uint32_t af[2][4];
#pragma unroll
            for (int mi = 0; mi < 2; mi++) {
                const float* p0 = pa + (wm * 32 + mi * 16 + g) * 32 + ch;
                float2 lo = *(const float2*)p0;
                float2 hi = *(const float2*)(p0 + 8 * 32);
                af[mi][0] = f2u(lo.x); af[mi][1] = f2u(hi.x);
                af[mi][2] = f2u(lo.y); af[mi][3] = f2u(hi.y);
            }
#pragma unroll
            for (int ni = 0; ni < 8; ni++) {
                float2 bv = *(const float2*)(pb + (wn * 64 + ni * 8 + g) * 32 + ch);
                uint32_t b0 = f2u(bv.x), b1 = f2u(bv.y);
                mma8(acc[0][ni], af[0], b0, b1);
                mma8(acc[1][ni], af[1], b0, b1);
            }
        }
        __syncthreads();
    }

    // epilogue
    const int p0i = (q < 2) ? 4 * q : 4 * q - 7;   // interleaved pos of k=2q
#pragma unroll
    for (int mi = 0; mi < 2; mi++) {
        int r0 = m0 + wm * 32 + mi * 16 + g, r1 = r0 + 8;
#pragma unroll
        for (int ni = 0; ni < 8; ni++) {
            int cb = n0 + wn * 64 + ni * 8;
            int c0 = cb + 2 * q;
            float bx = __ldg(bias + c0), by = __ldg(bias + c0 + 1);
            float v00 = acc[mi][ni][0] + bx, v01 = acc[mi][ni][1] + by;
            float v10 = acc[mi][ni][2] + bx, v11 = acc[mi][ni][3] + by;
            if (QKV) {
                if (which == 0) { v00 *= 0.125f; v01 *= 0.125f; v10 *= 0.125f; v11 *= 0.125f; }
                v00 = u2f(tf32b(v00)); v01 = u2f(tf32b(v01));
                v10 = u2f(tf32b(v10)); v11 = u2f(tf32b(v11));
                int h = cb >> 6;
                int bb0 = r0 >> 10, nn0 = r0 & (N_ - 1);
                int bb1 = r1 >> 10, nn1 = r1 & (N_ - 1);
                float* d0 = C + (((size_t)bb0 * H_ + h) * N_ + nn0) * D_ + (cb & 63);
                float* d1 = C + (((size_t)bb1 * H_ + h) * N_ + nn1) * D_ + (cb & 63);
                if (which < 2) {  // Q,K: d-interleaved
                    d0[p0i] = v00; d0[p0i + 2] = v01;
                    d1[p0i] = v10; d1[p0i + 2] = v11;
                } else {          // V: plain
                    *(float2*)(d0 + 2 * q) = make_float2(v00, v01);
                    *(float2*)(d1 + 2 * q) = make_float2(v10, v11);
                }
            } else {
                *(float2*)(C + (size_t)r0 * E_ + c0) = make_float2(v00, v01);
                *(float2*)(C + (size_t)r1 * E_ + c0) = make_float2(v10, v11);
            }
        }
    }
}

// ---------------------------------------------------------------------------
// Flash attention (R4 structure). Q/K interleaved in gmem (Q pre-scaled).
// smem floats: Qs[128*64] @0 (swizzled), Ks 2x[64*64] @8192 (swizzled),
// Vs 2x[64*72] @16384 (plain rows=key). Q/K frag loads LDS.64, V LDS.32 x2.
// 8 warps; warp = 16 q-rows x 64 keys; P stays in registers (shuffle transpose).
// ---------------------------------------------------------------------------
#define AK_OFF 8192
#define AV_OFF 16384
#define ATTN_SMEM ((AV_OFF + 2 * 64 * 72) * 4)   // 102400 B

__global__ __launch_bounds__(256, 2) void attn_mma(
    const float* __restrict__ Q, const float* __restrict__ K,
    const float* __restrict__ V, float* __restrict__ O)
{
    extern __shared__ float sm[];
    const uint32_t sb = smem_u32(sm);
    const int tid = threadIdx.x;
    const int wid = tid >> 5, lane = tid & 31;
    const int g = lane >> 2, q = lane & 3;
    const int bh = blockIdx.y;
    const int q0 = blockIdx.x * 128;

    const float* Qb = Q + (size_t)bh * N_ * D_;
    const float* Kb = K + (size_t)bh * N_ * D_;
    const float* Vb = V + (size_t)bh * N_ * D_;

    // Q -> smem (cp.async, group-XOR swizzle)
#pragma unroll
    for (int i = 0; i < 8; i++) {
        int c = tid + i * 256;              // 2048 16B chunks
        int row = c >> 4, c4 = c & 15;
        CP16(sb + (uint32_t)(row * 64 + (c4 ^ ((row & 3) << 1)) * 4) * 4,
             Qb + (size_t)(q0 + row) * D_ + c4 * 4);
    }
    CP_COMMIT();

    auto issueKV = [&](int ck) {
        int s = ck & 1;
        uint32_t kb = sb + (uint32_t)(AK_OFF + s * 64 * 64) * 4;
        uint32_t vb = sb + (uint32_t)(AV_OFF + s * 64 * 72) * 4;
        const float* Kc = Kb + (size_t)ck * 64 * D_;
        const float* Vc = Vb + (size_t)ck * 64 * D_;
#pragma unroll
        for (int i = 0; i < 4; i++) {
            int c = tid + i * 256;          // 1024 chunks each
            int row = c >> 4, c4 = c & 15;
            CP16(kb + (uint32_t)(row * 64 + (c4 ^ ((row & 3) << 1)) * 4) * 4,
                 Kc + (size_t)row * D_ + c4 * 4);
            CP16(vb + (uint32_t)(row * 72 + c4 * 4) * 4,
                 Vc + (size_t)row * D_ + c4 * 4);
        }
    };
    issueKV(0); CP_COMMIT();

    cp_wait<1>();   // Q done (K0/V0 may still be in flight)
    __syncthreads();

    // Register-resident Q fragments (pre-scaled, interleaved): LDS.64
    uint32_t qf[8][4];
#pragma unroll
    for (int kc = 0; kc < 8; kc++) {
        const int ch = (kc ^ (g & 3)) * 8 + 2 * q;
        const float* p0 = sm + (wid * 16 + g) * 64 + ch;
        float2 lo = *(const float2*)p0;
        float2 hi = *(const float2*)(p0 + 8 * 64);
        qf[kc][0] = f2u(lo.x); qf[kc][1] = f2u(hi.x);
        qf[kc][2] = f2u(lo.y); qf[kc][3] = f2u(hi.y);
    }

    float of[8][4];
#pragma unroll
    for (int ni = 0; ni < 8; ni++)
#pragma unroll
        for (int r = 0; r < 4; r++) of[ni][r] = 0.0f;
    float mA = -INFINITY, mB = -INFINITY, lA = 0.0f, lB = 0.0f;

    for (int ck = 0; ck < N_ / 64; ck++) {
        if (ck + 1 < N_ / 64) issueKV(ck + 1);
        CP_COMMIT();
        cp_wait<1>();
        __syncthreads();
        const float* Ksp = sm + AK_OFF + (ck & 1) * 64 * 64;
        const float* Vsp = sm + AV_OFF + (ck & 1) * 64 * 72;

        // S = (Q/8) K^T   (LDS.64 B-fragments)
        float sf[8][4];
#pragma unroll
        for (int ni = 0; ni < 8; ni++)
#pragma unroll
            for (int r = 0; r < 4; r++) sf[ni][r] = 0.0f;
#pragma unroll
        for (int kc = 0; kc < 8; kc++) {
            const int ch = (kc ^ (g & 3)) * 8 + 2 * q;
#pragma unroll
            for (int ni = 0; ni < 8; ni++) {
                float2 bv = *(const float2*)(Ksp + (ni * 8 + g) * 64 + ch);
                mma8(sf[ni], qf[kc], f2u(bv.x), f2u(bv.y));
            }
        }

        // Online softmax (rows rA = wid*16+g, rB = rA+8)
        float mxA = -INFINITY, mxB = -INFINITY;
#pragma unroll
        for (int ni = 0; ni < 8; ni++) {
            mxA = fmaxf(mxA, fmaxf(sf[ni][0], sf[ni][1]));
            mxB = fmaxf(mxB, fmaxf(sf[ni][2], sf[ni][3]));
        }
        mxA = fmaxf(mxA, __shfl_xor_sync(0xffffffffu, mxA, 1));
        mxA = fmaxf(mxA, __shfl_xor_sync(0xffffffffu, mxA, 2));
        mxB = fmaxf(mxB, __shfl_xor_sync(0xffffffffu, mxB, 1));
        mxB = fmaxf(mxB, __shfl_xor_sync(0xffffffffu, mxB, 2));
        float nmA = fmaxf(mA, mxA), nmB = fmaxf(mB, mxB);
        float cA = fexp(mA - nmA), cB = fexp(mB - nmB);
        float suA = 0.0f, suB = 0.0f;
#pragma unroll
        for (int ni = 0; ni < 8; ni++) {
            sf[ni][0] = fexp(sf[ni][0] - nmA);
            sf[ni][1] = fexp(sf[ni][1] - nmA);
            sf[ni][2] = fexp(sf[ni][2] - nmB);
            sf[ni][3] = fexp(sf[ni][3] - nmB);
            suA += sf[ni][0] + sf[ni][1];
            suB += sf[ni][2] + sf[ni][3];
        }
        suA += __shfl_xor_sync(0xffffffffu, suA, 1);
        suA += __shfl_xor_sync(0xffffffffu, suA, 2);
        suB += __shfl_xor_sync(0xffffffffu, suB, 1);
        suB += __shfl_xor_sync(0xffffffffu, suB, 2);
        lA = lA * cA + suA; lB = lB * cB + suB;
        mA = nmA; mB = nmB;
#pragma unroll
        for (int ni = 0; ni < 8; ni++) {
            of[ni][0] *= cA; of[ni][1] *= cA;
            of[ni][2] *= cB; of[ni][3] *= cB;
        }

        // O += P @ V : shuffle-transpose sf -> A fragment, V rows=key from smem
        const int srcl = (lane & 28) | (q >> 1);
        const bool odd = (q & 1);
#pragma unroll
        for (int kc = 0; kc < 8; kc++) {
            float e0 = __shfl_sync(0xffffffffu, sf[kc][0], srcl);
            float o0 = __shfl_sync(0xffffffffu, sf[kc][1], srcl);
            float e1 = __shfl_sync(0xffffffffu, sf[kc][2], srcl);
            float o1 = __shfl_sync(0xffffffffu, sf[kc][3], srcl);
            float e2 = __shfl_sync(0xffffffffu, sf[kc][0], srcl + 2);
            float o2 = __shfl_sync(0xffffffffu, sf[kc][1], srcl + 2);
            float e3 = __shfl_sync(0xffffffffu, sf[kc][2], srcl + 2);
            float o3 = __shfl_sync(0xffffffffu, sf[kc][3], srcl + 2);
            uint32_t a[4];
            a[0] = tf32b(odd ? o0 : e0);
            a[1] = tf32b(odd ? o1 : e1);
            a[2] = tf32b(odd ? o2 : e2);
            a[3] = tf32b(odd ? o3 : e3);
#pragma unroll
            for (int ni = 0; ni < 8; ni++) {
                const float* rb = Vsp + (kc * 8 + q) * 72 + ni * 8 + g;
                mma8(of[ni], a, f2u(rb[0]), f2u(rb[4 * 72]));
            }
        }
        __syncthreads();   // all reads of this K/V buffer done before next issue
    }

    // Epilogue -> AO [b, n, E], tf32-rounded + e-interleaved (for out-proj)
    const int bb = bh / H_, hh = bh - bb * H_;
    const int p0i = (q < 2) ? 4 * q : 4 * q - 7;
    float iA = 1.0f / lA, iB = 1.0f / lB;
    int rA = q0 + wid * 16 + g, rB = rA + 8;
#pragma unroll
    for (int ni = 0; ni < 8; ni++) {
        float* dA = O + ((size_t)(bb * N_ + rA)) * E_ + hh * D_ + ni * 8;
        float* dB = O + ((size_t)(bb * N_ + rB)) * E_ + hh * D_ + ni * 8;
        dA[p0i]     = u2f(tf32b(of[ni][0] * iA));
        dA[p0i + 2] = u2f(tf32b(of[ni][1] * iA));
        dB[p0i]     = u2f(tf32b(of[ni][2] * iB));
        dB[p0i + 2] = u2f(tf32b(of[ni][3] * iB));
    }
}

// ---------------------------------------------------------------------------
extern "C" void kernel_launch(void* const* d_in, const int* in_sizes, int n_in,
                              void* d_out, int out_size)
{
    const float* x  = (const float*)d_in[0];
    const float* Wq = (const float*)d_in[1];
    const float* bq = (const float*)d_in[2];
    const float* Wk = (const float*)d_in[3];
    const float* bk = (const float*)d_in[4];
    const float* Wv = (const float*)d_in[5];
    const float* bv = (const float*)d_in[6];
    const float* Wo = (const float*)d_in[7];
    const float* bo = (const float*)d_in[8];
    float* out = (float*)d_out;

    float *Qp, *Kp, *Vp, *AOp, *Xr, *Wr;
    cudaGetSymbolAddress((void**)&Qp,  g_Q);
    cudaGetSymbolAddress((void**)&Kp,  g_K);
    cudaGetSymbolAddress((void**)&Vp,  g_V);
    cudaGetSymbolAddress((void**)&AOp, g_AO);
    cudaGetSymbolAddress((void**)&Xr,  g_Xr);
    cudaGetSymbolAddress((void**)&Wr,  g_Wr);

    cudaFuncSetAttribute(tf32_gemm<true>,
                         cudaFuncAttributeMaxDynamicSharedMemorySize, GEMM_SMEM);
    cudaFuncSetAttribute(tf32_gemm<false>,
                         cudaFuncAttributeMaxDynamicSharedMemorySize, GEMM_SMEM);
    cudaFuncSetAttribute(attn_mma,
                         cudaFuncAttributeMaxDynamicSharedMemorySize, ATTN_SMEM);

    // Prepass: round + interleave
    {
        int n8x = TOK * E_ / 8, n8w = E_ * E_ / 8;
        prep8_kernel<<<(n8x + 255) / 256, 256>>>((const float4*)x, (float4*)Xr, n8x);
        prep8_kernel<<<(n8w + 255) / 256, 256>>>((const float4*)Wq, (float4*)(Wr + 0 * (size_t)E_ * E_), n8w);
        prep8_kernel<<<(n8w + 255) / 256, 256>>>((const float4*)Wk, (float4*)(Wr + 1 * (size_t)E_ * E_), n8w);
        prep8_kernel<<<(n8w + 255) / 256, 256>>>((const float4*)Wv, (float4*)(Wr + 2 * (size_t)E_ * E_), n8w);
        prep8_kernel<<<(n8w + 255) / 256, 256>>>((const float4*)Wo, (float4*)(Wr + 3 * (size_t)E_ * E_), n8w);
    }

    // Fused QKV projection
    dim3 gqkv(TOK / 128, 18);
    tf32_gemm<true><<<gqkv, 256, GEMM_SMEM>>>(Xr, Wr, bq, bk, bv, Qp, Kp, Vp);

    // Attention
    dim3 ga(N_ / 128, B_ * H_);
    attn_mma<<<ga, 256, ATTN_SMEM>>>(Qp, Kp, Vp, AOp);

    // Output projection
    dim3 go(TOK / 128, E_ / 128);
    tf32_gemm<false><<<go, 256, GEMM_SMEM>>>(
        AOp, Wr + 3 * (size_t)E_ * E_, bo, bo, bo, out, out, out);
}

// round 7
// speedup vs baseline: 1.4733x; 1.4733x over previous
#include <cuda_runtime.h>
#include <math.h>
#include <cstdint>

#define B_   16
#define N_   1024
#define E_   768
#define H_   12
#define D_   64
#define TOK  (B_ * N_)

// Scratch (no allocations allowed).
__device__ float g_Q [(size_t)B_ * H_ * N_ * D_];   // [b*H+h][n][d], tf32-rounded
__device__ float g_K [(size_t)B_ * H_ * N_ * D_];
__device__ float g_V [(size_t)B_ * H_ * N_ * D_];
__device__ float g_AO[(size_t)TOK * E_];            // [b][n][e], tf32-rounded
__device__ float g_Xr[(size_t)TOK * E_];            // tf32-rounded x
__device__ float g_Wr[4][(size_t)E_ * E_];          // tf32-rounded Wq,Wk,Wv,Wo

// ---------------------------------------------------------------------------
// helpers
// ---------------------------------------------------------------------------
__device__ __forceinline__ uint32_t smem_u32(const void* p) {
    uint32_t a;
    asm("{ .reg .u64 t; cvta.to.shared.u64 t, %1; cvt.u32.u64 %0, t; }" : "=r"(a) : "l"(p));
    return a;
}
__device__ __forceinline__ uint32_t tf32b(float x) {
    uint32_t u;
    asm("cvt.rna.tf32.f32 %0, %1;" : "=r"(u) : "f"(x));
    return u;
}
__device__ __forceinline__ float u2f(uint32_t u) { return __uint_as_float(u); }
__device__ __forceinline__ uint32_t f2u(float f) { return __float_as_uint(f); }

__device__ __forceinline__ void mma8(float* c, const uint32_t* a,
                                     uint32_t b0, uint32_t b1) {
    asm volatile(
        "mma.sync.aligned.m16n8k8.row.col.f32.tf32.tf32.f32 "
        "{%0,%1,%2,%3}, {%4,%5,%6,%7}, {%8,%9}, {%0,%1,%2,%3};\n"
        : "+f"(c[0]), "+f"(c[1]), "+f"(c[2]), "+f"(c[3])
        : "r"(a[0]), "r"(a[1]), "r"(a[2]), "r"(a[3]), "r"(b0), "r"(b1));
}

#define CP16(dst, src) \
    asm volatile("cp.async.cg.shared.global [%0], [%1], 16;" :: "r"(dst), "l"(src))
#define CP_COMMIT() asm volatile("cp.async.commit_group;" ::: "memory")
template <int N>
__device__ __forceinline__ void cp_wait() {
    asm volatile("cp.async.wait_group %0;" :: "n"(N) : "memory");
}

// Fast exp on the FMA pipe (no MUFU).
__device__ __forceinline__ float fexp(float x) {
    x = fmaxf(x, -80.0f);
    float t = x * 1.4426950408889634f;
    float z = t + 12582912.0f;
    int   e = __float_as_int(z);
    float f = t - (z - 12582912.0f);
    float p = 1.3333558e-3f;
    p = fmaf(p, f, 9.6181291e-3f);
    p = fmaf(p, f, 5.5504109e-2f);
    p = fmaf(p, f, 2.4022651e-1f);
    p = fmaf(p, f, 6.9314718e-1f);
    p = fmaf(p, f, 1.0f);
    return __int_as_float(__float_as_int(p) + (e << 23));
}

// ---------------------------------------------------------------------------
// Prepass: tf32 RN round for x and all 4 weights in ONE launch.
// ---------------------------------------------------------------------------
#define N4X (TOK * E_ / 4)
#define N4W (E_ * E_ / 4)

__global__ __launch_bounds__(256) void round_all_kernel(
    const float4* __restrict__ x,
    const float4* __restrict__ wq, const float4* __restrict__ wk,
    const float4* __restrict__ wv, const float4* __restrict__ wo,
    float4* __restrict__ xr, float4* __restrict__ wr)
{
    int i = blockIdx.x * blockDim.x + threadIdx.x;
    const float4* src;
    float4* dst;
    int off;
    if (i < N4X) {
        src = x; dst = xr; off = i;
    } else {
        int j = i - N4X;
        if (j >= 4 * N4W) return;
        int w = j / N4W;
        off = j - w * N4W;
        src = (w == 0) ? wq : (w == 1) ? wk : (w == 2) ? wv : wo;
        dst = wr + (size_t)w * N4W;
    }
    float4 v = src[off];
    v.x = u2f(tf32b(v.x)); v.y = u2f(tf32b(v.y));
    v.z = u2f(tf32b(v.z)); v.w = u2f(tf32b(v.w));
    dst[off] = v;
}

// ---------------------------------------------------------------------------
// tf32 mma.sync GEMM, cp.async 3-stage pipeline.
// BM=BN=128, BK=32 (rows of 32 floats, stride 36 => conflict-free LDS.32).
// QKV=true: fused Q/K/V (grid.y = 18), epilogue rounds + scatters to [b,h,n,d].
// QKV=false: plain C[t,e] = A.W^T + b, no rounding.
// ---------------------------------------------------------------------------
#define GSTG  (256 * 36)                 // floats per stage (A 128x36 + B 128x36)
#define GEMM_SMEM (3 * GSTG * 4)         // 110592 B

template <bool QKV>
__global__ __launch_bounds__(256, 2) void tf32_gemm(
    const float* __restrict__ A, const float* __restrict__ Wbase,
    const float* __restrict__ bp0, const float* __restrict__ bp1,
    const float* __restrict__ bp2,
    float* __restrict__ C0, float* __restrict__ C1, float* __restrict__ C2)
{
    extern __shared__ float sm[];
    const uint32_t sb = smem_u32(sm);
    const int tid = threadIdx.x;
    const int wid = tid >> 5, lane = tid & 31;
    const int g = lane >> 2, q = lane & 3;
    const int wm = wid >> 1, wn = wid & 1;
    const int m0 = blockIdx.x * 128;

    int n0;
    const float* W;
    const float* bias;
    float* C;
    if (QKV) {
        int which = blockIdx.y / 6;
        n0 = (blockIdx.y % 6) * 128;
        W = Wbase + (size_t)which * E_ * E_;
        bias = (which == 0) ? bp0 : (which == 1) ? bp1 : bp2;
        C = (which == 0) ? C0 : (which == 1) ? C1 : C2;
    } else {
        n0 = blockIdx.y * 128;
        W = Wbase; bias = bp0; C = C0;
    }

    auto issue = [&](int ko) {
        uint32_t base = sb + (uint32_t)(ko % 3) * GSTG * 4;
        const float* Ab = A + (size_t)m0 * E_ + ko * 32;
        const float* Wb = W + (size_t)n0 * E_ + ko * 32;
#pragma unroll
        for (int i = 0; i < 4; i++) {
            int c = tid + i * 256;          // 0..1023
            int row = c >> 3, c4 = c & 7;
            CP16(base + (uint32_t)(row * 36 + c4 * 4) * 4,
                 Ab + (size_t)row * E_ + c4 * 4);
            CP16(base + (uint32_t)(128 * 36 + row * 36 + c4 * 4) * 4,
                 Wb + (size_t)row * E_ + c4 * 4);
        }
    };

    float acc[2][8][4];
#pragma unroll
    for (int mi = 0; mi < 2; mi++)
#pragma unroll
        for (int ni = 0; ni < 8; ni++)
#pragma unroll
            for (int r = 0; r < 4; r++) acc[mi][ni][r] = 0.0f;

    issue(0); CP_COMMIT();
    issue(1); CP_COMMIT();

    for (int ko = 0; ko < E_ / 32; ko++) {
        if (ko + 2 < E_ / 32) issue(ko + 2);
        CP_COMMIT();
        cp_wait<2>();
        __syncthreads();
        const float* pa = sm + (ko % 3) * GSTG;
        const float* pb = pa + 128 * 36;
#pragma unroll
        for (int kc = 0; kc < 4; kc++) {
            uint32_t af[2][4];
#pragma unroll
            for (int mi = 0; mi < 2; mi++) {
                const float* r0 = pa + (wm * 32 + mi * 16 + g) * 36 + kc * 8;
                const float* r1 = r0 + 8 * 36;
                af[mi][0] = f2u(r0[q]);     af[mi][1] = f2u(r1[q]);
                af[mi][2] = f2u(r0[q + 4]); af[mi][3] = f2u(r1[q + 4]);
            }
#pragma unroll
            for (int ni = 0; ni < 8; ni++) {
                const float* rb = pb + (wn * 64 + ni * 8 + g) * 36 + kc * 8;
                uint32_t b0 = f2u(rb[q]), b1 = f2u(rb[q + 4]);
                mma8(acc[0][ni], af[0], b0, b1);
                mma8(acc[1][ni], af[1], b0, b1);
            }
        }
        __syncthreads();
    }

    // epilogue
#pragma unroll
    for (int mi = 0; mi < 2; mi++) {
        int r0 = m0 + wm * 32 + mi * 16 + g, r1 = r0 + 8;
#pragma unroll
        for (int ni = 0; ni < 8; ni++) {
            int cb = n0 + wn * 64 + ni * 8;
            int c0 = cb + 2 * q;
            float bx = __ldg(bias + c0), by = __ldg(bias + c0 + 1);
            float v00 = acc[mi][ni][0] + bx, v01 = acc[mi][ni][1] + by;
            float v10 = acc[mi][ni][2] + bx, v11 = acc[mi][ni][3] + by;
            if (QKV) {
                v00 = u2f(tf32b(v00)); v01 = u2f(tf32b(v01));
                v10 = u2f(tf32b(v10)); v11 = u2f(tf32b(v11));
                int h = cb >> 6, d0 = (cb & 63) + 2 * q;
                int bb0 = r0 >> 10, nn0 = r0 & (N_ - 1);
                int bb1 = r1 >> 10, nn1 = r1 & (N_ - 1);
                *(float2*)(C + (((size_t)bb0 * H_ + h) * N_ + nn0) * D_ + d0) =
                    make_float2(v00, v01);
                *(float2*)(C + (((size_t)bb1 * H_ + h) * N_ + nn1) * D_ + d0) =
                    make_float2(v10, v11);
            } else {
                *(float2*)(C + (size_t)r0 * E_ + c0) = make_float2(v00, v01);
                *(float2*)(C + (size_t)r1 * E_ + c0) = make_float2(v10, v11);
            }
        }
    }
}

// ---------------------------------------------------------------------------
// Flash attention: cp.async double-buffered K/V, P kept in registers
// (shuffle-transposed S fragments feed the PV mma directly).
// Q [128][68], K 2x[64][68] (rows=key, cols=d), V 2x[64][72] (rows=key, cols=d).
// Warp = 16 q-rows x 64 keys. All fragment loads are conflict-free LDS.32.
// ---------------------------------------------------------------------------
#define AQ_OFF 0
#define AK_OFF (128 * 68)                 // 8704
#define AV_OFF (AK_OFF + 2 * 64 * 68)     // 17408
#define ATTN_FLOATS (AV_OFF + 2 * 64 * 72)
#define ATTN_SMEM (ATTN_FLOATS * 4)       // 106496 B

__global__ __launch_bounds__(256, 2) void attn_mma(
    const float* __restrict__ Q, const float* __restrict__ K,
    const float* __restrict__ V, float* __restrict__ O)
{
    extern __shared__ float sm[];
    const uint32_t sb = smem_u32(sm);
    const int tid = threadIdx.x;
    const int wid = tid >> 5, lane = tid & 31;
    const int g = lane >> 2, q = lane & 3;
    const int bh = blockIdx.y;
    const int q0 = blockIdx.x * 128;

    const float* Qb = Q + (size_t)bh * N_ * D_;
    const float* Kb = K + (size_t)bh * N_ * D_;
    const float* Vb = V + (size_t)bh * N_ * D_;

    // Q tile -> smem (async, one group)
#pragma unroll
    for (int i = 0; i < 8; i++) {
        int c = tid + i * 256;              // 2048 16B chunks
        int row = c >> 4, c4 = c & 15;
        CP16(sb + (uint32_t)(AQ_OFF + row * 68 + c4 * 4) * 4,
             Qb + (size_t)(q0 + row) * D_ + c4 * 4);
    }
    CP_COMMIT();

    auto issueKV = [&](int ck) {
        int s = ck & 1;
        uint32_t kb = sb + (uint32_t)(AK_OFF + s * 64 * 68) * 4;
        uint32_t vb = sb + (uint32_t)(AV_OFF + s * 64 * 72) * 4;
        const float* Kc = Kb + (size_t)ck * 64 * D_;
        const float* Vc = Vb + (size_t)ck * 64 * D_;
#pragma unroll
        for (int i = 0; i < 4; i++) {
            int c = tid + i * 256;          // 1024 chunks each
            int row = c >> 4, c4 = c & 15;
            CP16(kb + (uint32_t)(row * 68 + c4 * 4) * 4,
                 Kc + (size_t)row * D_ + c4 * 4);
            CP16(vb + (uint32_t)(row * 72 + c4 * 4) * 4,
                 Vc + (size_t)row * D_ + c4 * 4);
        }
    };
    issueKV(0); CP_COMMIT();

    // wait for Q (kv0 may still be in flight), load Q fragments (pre-scaled)
    cp_wait<1>();
    __syncthreads();
    uint32_t qf[8][4];
#pragma unroll
    for (int kc = 0; kc < 8; kc++) {
        const float* r0 = sm + AQ_OFF + (wid * 16 + g) * 68 + kc * 8;
        const float* r1 = r0 + 8 * 68;
        qf[kc][0] = f2u(r0[q] * 0.125f);     qf[kc][1] = f2u(r1[q] * 0.125f);
        qf[kc][2] = f2u(r0[q + 4] * 0.125f); qf[kc][3] = f2u(r1[q + 4] * 0.125f);
    }

    float of[8][4];
#pragma unroll
    for (int ni = 0; ni < 8; ni++)
#pragma unroll
        for (int r = 0; r < 4; r++) of[ni][r] = 0.0f;
    float mA = -INFINITY, mB = -INFINITY, lA = 0.0f, lB = 0.0f;

    for (int ck = 0; ck < N_ / 64; ck++) {
        if (ck + 1 < N_ / 64) issueKV(ck + 1);
        CP_COMMIT();
        cp_wait<1>();
        __syncthreads();
        const float* Ksp = sm + AK_OFF + (ck & 1) * 64 * 68;
        const float* Vsp = sm + AV_OFF + (ck & 1) * 64 * 72;

        // S = (Q/8) K^T
        float sf[8][4];
#pragma unroll
        for (int ni = 0; ni < 8; ni++)
#pragma unroll
            for (int r = 0; r < 4; r++) sf[ni][r] = 0.0f;
#pragma unroll
        for (int kc = 0; kc < 8; kc++) {
#pragma unroll
            for (int ni = 0; ni < 8; ni++) {
                const float* rb = Ksp + (ni * 8 + g) * 68 + kc * 8;
                mma8(sf[ni], qf[kc], f2u(rb[q]), f2u(rb[q + 4]));
            }
        }

        // Online softmax (rows rA = wid*16+g, rB = rA+8)
        float mxA = -INFINITY, mxB = -INFINITY;
#pragma unroll
        for (int ni = 0; ni < 8; ni++) {
            mxA = fmaxf(mxA, fmaxf(sf[ni][0], sf[ni][1]));
            mxB = fmaxf(mxB, fmaxf(sf[ni][2], sf[ni][3]));
        }
        mxA = fmaxf(mxA, __shfl_xor_sync(0xffffffffu, mxA, 1));
        mxA = fmaxf(mxA, __shfl_xor_sync(0xffffffffu, mxA, 2));
        mxB = fmaxf(mxB, __shfl_xor_sync(0xffffffffu, mxB, 1));
        mxB = fmaxf(mxB, __shfl_xor_sync(0xffffffffu, mxB, 2));
        float nmA = fmaxf(mA, mxA), nmB = fmaxf(mB, mxB);
        float cA = fexp(mA - nmA), cB = fexp(mB - nmB);
        float suA = 0.0f, suB = 0.0f;
#pragma unroll
        for (int ni = 0; ni < 8; ni++) {
            sf[ni][0] = fexp(sf[ni][0] - nmA);
            sf[ni][1] = fexp(sf[ni][1] - nmA);
            sf[ni][2] = fexp(sf[ni][2] - nmB);
            sf[ni][3] = fexp(sf[ni][3] - nmB);
            suA += sf[ni][0] + sf[ni][1];
            suB += sf[ni][2] + sf[ni][3];
        }
        suA += __shfl_xor_sync(0xffffffffu, suA, 1);
        suA += __shfl_xor_sync(0xffffffffu, suA, 2);
        suB += __shfl_xor_sync(0xffffffffu, suB, 1);
        suB += __shfl_xor_sync(0xffffffffu, suB, 2);
        lA = lA * cA + suA; lB = lB * cB + suB;
        mA = nmA; mB = nmB;
#pragma unroll
        for (int ni = 0; ni < 8; ni++) {
            of[ni][0] *= cA; of[ni][1] *= cA;
            of[ni][2] *= cB; of[ni][3] *= cB;
        }

        // O += P @ V : shuffle-transpose sf -> A fragment, V from smem
        const int srcl = (lane & 28) | (q >> 1);
        const bool odd = (q & 1);
#pragma unroll
        for (int kc = 0; kc < 8; kc++) {
            float e0 = __shfl_sync(0xffffffffu, sf[kc][0], srcl);
            float o0 = __shfl_sync(0xffffffffu, sf[kc][1], srcl);
            float e1 = __shfl_sync(0xffffffffu, sf[kc][2], srcl);
            float o1 = __shfl_sync(0xffffffffu, sf[kc][3], srcl);
            float e2 = __shfl_sync(0xffffffffu, sf[kc][0], srcl + 2);
            float o2 = __shfl_sync(0xffffffffu, sf[kc][1], srcl + 2);
            float e3 = __shfl_sync(0xffffffffu, sf[kc][2], srcl + 2);
            float o3 = __shfl_sync(0xffffffffu, sf[kc][3], srcl + 2);
            uint32_t a[4];
            a[0] = tf32b(odd ? o0 : e0);
            a[1] = tf32b(odd ? o1 : e1);
            a[2] = tf32b(odd ? o2 : e2);
            a[3] = tf32b(odd ? o3 : e3);
#pragma unroll
            for (int ni = 0; ni < 8; ni++) {
                const float* rb = Vsp + (kc * 8 + q) * 72 + ni * 8 + g;
                mma8(of[ni], a, f2u(rb[0]), f2u(rb[4 * 72]));
            }
        }
        __syncthreads();   // all reads of this K/V buffer done before next issue
    }

    // Epilogue -> AO [b, n, E], tf32-rounded for the output projection
    const int bb = bh / H_, hh = bh - bb * H_;
    float iA = 1.0f / lA, iB = 1.0f / lB;
    int rA = q0 + wid * 16 + g, rB = rA + 8;
#pragma unroll
    for (int ni = 0; ni < 8; ni++) {
        int d0 = ni * 8 + 2 * q;
        float2 vA = make_float2(u2f(tf32b(of[ni][0] * iA)), u2f(tf32b(of[ni][1] * iA)));
        float2 vB = make_float2(u2f(tf32b(of[ni][2] * iB)), u2f(tf32b(of[ni][3] * iB)));
        *(float2*)(O + ((size_t)(bb * N_ + rA)) * E_ + hh * D_ + d0) = vA;
        *(float2*)(O + ((size_t)(bb * N_ + rB)) * E_ + hh * D_ + d0) = vB;
    }
}

// ---------------------------------------------------------------------------
extern "C" void kernel_launch(void* const* d_in, const int* in_sizes, int n_in,
                              void* d_out, int out_size)
{
    const float* x  = (const float*)d_in[0];
    const float* Wq = (const float*)d_in[1];
    const float* bq = (const float*)d_in[2];
    const float* Wk = (const float*)d_in[3];
    const float* bk = (const float*)d_in[4];
    const float* Wv = (const float*)d_in[5];
    const float* bv = (const float*)d_in[6];
    const float* Wo = (const float*)d_in[7];
    const float* bo = (const float*)d_in[8];
    float* out = (float*)d_out;

    float *Qp, *Kp, *Vp, *AOp, *Xr, *Wr;
    cudaGetSymbolAddress((void**)&Qp,  g_Q);
    cudaGetSymbolAddress((void**)&Kp,  g_K);
    cudaGetSymbolAddress((void**)&Vp,  g_V);
    cudaGetSymbolAddress((void**)&AOp, g_AO);
    cudaGetSymbolAddress((void**)&Xr,  g_Xr);
    cudaGetSymbolAddress((void**)&Wr,  g_Wr);

    cudaFuncSetAttribute(tf32_gemm<true>,
                         cudaFuncAttributeMaxDynamicSharedMemorySize, GEMM_SMEM);
    cudaFuncSetAttribute(tf32_gemm<false>,
                         cudaFuncAttributeMaxDynamicSharedMemorySize, GEMM_SMEM);
    cudaFuncSetAttribute(attn_mma,
                         cudaFuncAttributeMaxDynamicSharedMemorySize, ATTN_SMEM);

    // tf32 RN rounding prepass (single launch for x + 4 weights)
    {
        int total = N4X + 4 * N4W;
        round_all_kernel<<<(total + 255) / 256, 256>>>(
            (const float4*)x, (const float4*)Wq, (const float4*)Wk,
            (const float4*)Wv, (const float4*)Wo, (float4*)Xr, (float4*)Wr);
    }

    // Fused QKV projection
    dim3 gqkv(TOK / 128, 18);
    tf32_gemm<true><<<gqkv, 256, GEMM_SMEM>>>(Xr, Wr, bq, bk, bv, Qp, Kp, Vp);

    // Attention
    dim3 ga(N_ / 128, B_ * H_);
    attn_mma<<<ga, 256, ATTN_SMEM>>>(Qp, Kp, Vp, AOp);

    // Output projection
    dim3 go(TOK / 128, E_ / 128);
    tf32_gemm<false><<<go, 256, GEMM_SMEM>>>(
        AOp, Wr + 3 * (size_t)E_ * E_, bo, bo, bo, out, out, out);
}

// round 9
// speedup vs baseline: 3.0159x; 2.0470x over previous
#include <cuda_runtime.h>
#include <cuda_fp16.h>
#include <math.h>
#include <cstdint>

#define B_   16
#define N_   1024
#define E_   768
#define H_   12
#define D_   64
#define TOK  (B_ * N_)

// Scratch (no allocations). Q,K: [b*H+h][n][d] half, Q pre-scaled 0.125.
// VT: [b*H+h][d][n] half (transposed). AO: [b][n][e] half. Xh/Wh: half inputs.
__device__ __half g_Qh [(size_t)B_ * H_ * N_ * D_];
__device__ __half g_Kh [(size_t)B_ * H_ * N_ * D_];
__device__ __half g_VTh[(size_t)B_ * H_ * N_ * D_];
__device__ __half g_AOh[(size_t)TOK * E_];
__device__ __half g_Xh [(size_t)TOK * E_];
__device__ __half g_Wh [4][(size_t)E_ * E_];

// ---------------------------------------------------------------------------
__device__ __forceinline__ uint32_t smem_u32(const void* p) {
    uint32_t a;
    asm("{ .reg .u64 t; cvta.to.shared.u64 t, %1; cvt.u32.u64 %0, t; }" : "=r"(a) : "l"(p));
    return a;
}
__device__ __forceinline__ uint32_t h2pack(float lo, float hi) {
    __half2 t = __floats2half2_rn(lo, hi);
    return *reinterpret_cast<uint32_t*>(&t);
}

// m16n8k16 fp16 mma, fp32 accumulate
__device__ __forceinline__ void mma16(float* c, const uint32_t* a,
                                      uint32_t b0, uint32_t b1) {
    asm volatile(
        "mma.sync.aligned.m16n8k16.row.col.f32.f16.f16.f32 "
        "{%0,%1,%2,%3}, {%4,%5,%6,%7}, {%8,%9}, {%0,%1,%2,%3};\n"
        : "+f"(c[0]), "+f"(c[1]), "+f"(c[2]), "+f"(c[3])
        : "r"(a[0]), "r"(a[1]), "r"(a[2]), "r"(a[3]), "r"(b0), "r"(b1));
}

#define CP16(dst, src) \
    asm volatile("cp.async.cg.shared.global [%0], [%1], 16;" :: "r"(dst), "l"(src))
#define CP_COMMIT() asm volatile("cp.async.commit_group;" ::: "memory")
template <int N>
__device__ __forceinline__ void cp_wait() {
    asm volatile("cp.async.wait_group %0;" :: "n"(N) : "memory");
}

// Swizzled half2 fragment load: tile rows are 128B; row & 7 must equal g.
__device__ __forceinline__ uint32_t ld32sw(const char* tile, int row, int kch,
                                           int g, int q) {
    return *(const uint32_t*)(tile + row * 128 + ((kch ^ g) << 4) + 4 * q);
}

// Fast exp on the FMA pipe (no MUFU).
__device__ __forceinline__ float fexp(float x) {
    x = fmaxf(x, -80.0f);
    float t = x * 1.4426950408889634f;
    float z = t + 12582912.0f;
    int   e = __float_as_int(z);
    float f = t - (z - 12582912.0f);
    float p = 1.3333558e-3f;
    p = fmaf(p, f, 9.6181291e-3f);
    p = fmaf(p, f, 5.5504109e-2f);
    p = fmaf(p, f, 2.4022651e-1f);
    p = fmaf(p, f, 6.9314718e-1f);
    p = fmaf(p, f, 1.0f);
    return __int_as_float(__float_as_int(p) + (e << 23));
}

// ---------------------------------------------------------------------------
// Prepass: f32 -> f16 RN for x and all 4 weights in one launch. 8 elems/thread.
// ---------------------------------------------------------------------------
#define N8X (TOK * E_ / 8)
#define N8W (E_ * E_ / 8)

__global__ __launch_bounds__(256) void to_half_kernel(
    const float4* __restrict__ x,
    const float4* __restrict__ wq, const float4* __restrict__ wk,
    const float4* __restrict__ wv, const float4* __restrict__ wo,
    uint4* __restrict__ xh, uint4* __restrict__ wh)
{
    int i = blockIdx.x * blockDim.x + threadIdx.x;
    const float4* src;
    uint4* dst;
    int off;
    if (i < N8X) {
        src = x; dst = xh; off = i;
    } else {
        int j = i - N8X;
        if (j >= 4 * N8W) return;
        int w = j / N8W;
        off = j - w * N8W;
        src = (w == 0) ? wq : (w == 1) ? wk : (w == 2) ? wv : wo;
        dst = wh + (size_t)w * N8W;
    }
    float4 a = src[2 * off], b = src[2 * off + 1];
    uint4 o;
    o.x = h2pack(a.x, a.y); o.y = h2pack(a.z, a.w);
    o.z = h2pack(b.x, b.y); o.w = h2pack(b.z, b.w);
    dst[off] = o;
}

// ---------------------------------------------------------------------------
// fp16 mma GEMM: C[m,n] = A[m,:].W[n,:] + bias[n].  BM=BN=128, BK=64 halves.
// 256 thr (8 warps 4x2), warp tile 32x64. 3-stage cp.async, SW128 XOR swizzle.
// QKV=true: grid.y=18; which 0=Q (x0.125->half), 1=K (half), 2=V (half, transposed).
// QKV=false: float out + bias.
// ---------------------------------------------------------------------------
#define HSTG 32768                     // bytes/stage: A 16K + B 16K
#define GEMM_SMEM (3 * HSTG)           // 98304 B

template <bool QKV>
__global__ __launch_bounds__(256, 2) void h_gemm(
    const __half* __restrict__ A, const __half* __restrict__ Wbase,
    const float* __restrict__ bp0, const float* __restrict__ bp1,
    const float* __restrict__ bp2,
    __half* __restrict__ Qd, __half* __restrict__ Kd, __half* __restrict__ VTd,
    float* __restrict__ Cf)
{
    extern __shared__ char smc[];
    const uint32_t sb = smem_u32(smc);
    const int tid = threadIdx.x;
    const int wid = tid >> 5, lane = tid & 31;
    const int g = lane >> 2, q = lane & 3;
    const int wm = wid >> 1, wn = wid & 1;
    const int m0 = blockIdx.x * 128;

    int n0, which = 0;
    const __half* W;
    const float* bias;
    if (QKV) {
        which = blockIdx.y / 6;
        n0 = (blockIdx.y % 6) * 128;
        W = Wbase + (size_t)which * E_ * E_;
        bias = (which == 0) ? bp0 : (which == 1) ? bp1 : bp2;
    } else {
        n0 = blockIdx.y * 128;
        W = Wbase; bias = bp0;
    }

    auto issue = [&](int ko) {
        uint32_t base = sb + (uint32_t)(ko % 3) * HSTG;
        const __half* Ab = A + (size_t)m0 * E_ + ko * 64;
        const __half* Wb = W + (size_t)n0 * E_ + ko * 64;
#pragma unroll
        for (int i = 0; i < 4; i++) {
            int c = tid + i * 256;          // 0..1023
            int row = c >> 3, c4 = c & 7;
            uint32_t off = (uint32_t)(row * 128 + ((c4 ^ (row & 7)) << 4));
            CP16(base + off, Ab + (size_t)row * E_ + c4 * 8);
            CP16(base + 16384 + off, Wb + (size_t)row * E_ + c4 * 8);
        }
    };

    float acc[2][8][4];
#pragma unroll
    for (int mi = 0; mi < 2; mi++)
#pragma unroll
        for (int ni = 0; ni < 8; ni++)
#pragma unroll
            for (int r = 0; r < 4; r++) acc[mi][ni][r] = 0.0f;

    issue(0); CP_COMMIT();
    issue(1); CP_COMMIT();

    for (int ko = 0; ko < E_ / 64; ko++) {
        if (ko + 2 < E_ / 64) issue(ko + 2);
        CP_COMMIT();
        cp_wait<2>();
        __syncthreads();
        const char* pa = smc + (ko % 3) * HSTG;
        const char* pb = pa + 16384;
#pragma unroll
        for (int kc = 0; kc < 4; kc++) {
            uint32_t af[2][4];
#pragma unroll
            for (int mi = 0; mi < 2; mi++) {
                int rowA = wm * 32 + mi * 16 + g;
                af[mi][0] = ld32sw(pa, rowA,     kc * 2,     g, q);
                af[mi][1] = ld32sw(pa, rowA + 8, kc * 2,     g, q);
                af[mi][2] = ld32sw(pa, rowA,     kc * 2 + 1, g, q);
                af[mi][3] = ld32sw(pa, rowA + 8, kc * 2 + 1, g, q);
            }
#pragma unroll
            for (int ni = 0; ni < 8; ni++) {
                int rowB = wn * 64 + ni * 8 + g;
                uint32_t b0 = ld32sw(pb, rowB, kc * 2,     g, q);
                uint32_t b1 = ld32sw(pb, rowB, kc * 2 + 1, g, q);
                mma16(acc[0][ni], af[0], b0, b1);
                mma16(acc[1][ni], af[1], b0, b1);
            }
        }
        __syncthreads();
    }

    // epilogue
#pragma unroll
    for (int mi = 0; mi < 2; mi++) {
        int r0 = m0 + wm * 32 + mi * 16 + g, r1 = r0 + 8;
#pragma unroll
        for (int ni = 0; ni < 8; ni++) {
            int cb = n0 + wn * 64 + ni * 8;
            int c0 = cb + 2 * q;
            float bx = __ldg(bias + c0), by = __ldg(bias + c0 + 1);
            float v00 = acc[mi][ni][0] + bx, v01 = acc[mi][ni][1] + by;
            float v10 = acc[mi][ni][2] + bx, v11 = acc[mi][ni][3] + by;
            if (QKV) {
                int h = cb >> 6, d0 = (cb & 63) + 2 * q;
                int bb0 = r0 >> 10, nn0 = r0 & (N_ - 1);
                int bb1 = r1 >> 10, nn1 = r1 & (N_ - 1);
                if (which == 2) {   // V: transposed [bh][d][n], scalar stores
                    size_t vbase0 = ((size_t)bb0 * H_ + h) * D_;
                    size_t vbase1 = ((size_t)bb1 * H_ + h) * D_;
                    VTd[(vbase0 + d0)     * N_ + nn0] = __float2half_rn(v00);
                    VTd[(vbase0 + d0 + 1) * N_ + nn0] = __float2half_rn(v01);
                    VTd[(vbase1 + d0)     * N_ + nn1] = __float2half_rn(v10);
                    VTd[(vbase1 + d0 + 1) * N_ + nn1] = __float2half_rn(v11);
                } else {
                    __half* C = (which == 0) ? Qd : Kd;
                    if (which == 0) { v00 *= 0.125f; v01 *= 0.125f;
                                      v10 *= 0.125f; v11 *= 0.125f; }
                    uint32_t p0 = h2pack(v00, v01), p1 = h2pack(v10, v11);
                    *(uint32_t*)(C + (((size_t)bb0 * H_ + h) * N_ + nn0) * D_ + d0) = p0;
                    *(uint32_t*)(C + (((size_t)bb1 * H_ + h) * N_ + nn1) * D_ + d0) = p1;
                }
            } else {
                *(float2*)(Cf + (size_t)r0 * E_ + c0) = make_float2(v00, v01);
                *(float2*)(Cf + (size_t)r1 * E_ + c0) = make_float2(v10, v11);
            }
        }
    }
}

// ---------------------------------------------------------------------------
// Flash attention, fp16 k16 mma. Q [128][64h] @0 (16KB), K 2x[64][64h] @16384,
// VT 2x[64 d][64 keys] @32768. All rows 128B, SW128 XOR swizzle.
// 8 warps, warp = 16 q-rows x 64 keys. QK C-frags ARE the PV A-frags (cvt only).
// ---------------------------------------------------------------------------
#define AK_B 16384
#define AV_B 32768
#define ATTN_SMEM 49152

__global__ __launch_bounds__(256, 2) void attn_h(
    const __half* __restrict__ Q, const __half* __restrict__ K,
    const __half* __restrict__ VT, __half* __restrict__ O)
{
    extern __shared__ char smc[];
    const uint32_t sb = smem_u32(smc);
    const int tid = threadIdx.x;
    const int wid = tid >> 5, lane = tid & 31;
    const int g = lane >> 2, q = lane & 3;
    const int bh = blockIdx.y;
    const int q0 = blockIdx.x * 128;

    const __half* Qb = Q + (size_t)bh * N_ * D_ + (size_t)q0 * D_;
    const __half* Kb = K + (size_t)bh * N_ * D_;
    const __half* Vt = VT + (size_t)bh * D_ * N_;

    // Q -> smem (1024 16B chunks)
#pragma unroll
    for (int i = 0; i < 4; i++) {
        int c = tid + i * 256;
        int row = c >> 3, c4 = c & 7;
        CP16(sb + (uint32_t)(row * 128 + ((c4 ^ (row & 7)) << 4)),
             Qb + (size_t)row * D_ + c4 * 8);
    }
    CP_COMMIT();

    auto issueKV = [&](int ck) {
        uint32_t kb = sb + AK_B + (ck & 1) * 8192;
        uint32_t vb = sb + AV_B + (ck & 1) * 8192;
        const __half* Kc = Kb + (size_t)ck * 64 * D_;
        const __half* Vc = Vt + ck * 64;
#pragma unroll
        for (int i = 0; i < 2; i++) {
            int c = tid + i * 256;          // 512 chunks each
            int row = c >> 3, c4 = c & 7;
            uint32_t off = (uint32_t)(row * 128 + ((c4 ^ (row & 7)) << 4));
            CP16(kb + off, Kc + (size_t)row * D_ + c4 * 8);
            CP16(vb + off, Vc + (size_t)row * N_ + c4 * 8);
        }
    };
    issueKV(0); CP_COMMIT();

    cp_wait<1>();       // Q resident (KV0 may be in flight)
    __syncthreads();

    // Register-resident Q fragments (pre-scaled by 0.125 in gmem)
    uint32_t qf[4][4];
#pragma unroll
    for (int kc = 0; kc < 4; kc++) {
        int row = wid * 16 + g;
        qf[kc][0] = ld32sw(smc, row,     kc * 2,     g, q);
        qf[kc][1] = ld32sw(smc, row + 8, kc * 2,     g, q);
        qf[kc][2] = ld32sw(smc, row,     kc * 2 + 1, g, q);
        qf[kc][3] = ld32sw(smc, row + 8, kc * 2 + 1, g, q);
    }

    float of[8][4];
#pragma unroll
    for (int ni = 0; ni < 8; ni++)
#pragma unroll
        for (int r = 0; r < 4; r++) of[ni][r] = 0.0f;
    float mA = -INFINITY, mB = -INFINITY, lA = 0.0f, lB = 0.0f;

    for (int ck = 0; ck < N_ / 64; ck++) {
        if (ck + 1 < N_ / 64) issueKV(ck + 1);
        CP_COMMIT();
        cp_wait<1>();
        __syncthreads();
        const char* Ksp = smc + AK_B + (ck & 1) * 8192;
        const char* Vsp = smc + AV_B + (ck & 1) * 8192;

        // S = (Q/8) K^T
        float sf[8][4];
#pragma unroll
        for (int ni = 0; ni < 8; ni++)
#pragma unroll
            for (int r = 0; r < 4; r++) sf[ni][r] = 0.0f;
#pragma unroll
        for (int kc = 0; kc < 4; kc++) {
#pragma unroll
            for (int ni = 0; ni < 8; ni++) {
                int rowB = ni * 8 + g;
                uint32_t b0 = ld32sw(Ksp, rowB, kc * 2,     g, q);
                uint32_t b1 = ld32sw(Ksp, rowB, kc * 2 + 1, g, q);
                mma16(sf[ni], qf[kc], b0, b1);
            }
        }

        // Online softmax (rows rA = wid*16+g, rB = rA+8)
        float mxA = -INFINITY, mxB = -INFINITY;
#pragma unroll
        for (int ni = 0; ni < 8; ni++) {
            mxA = fmaxf(mxA, fmaxf(sf[ni][0], sf[ni][1]));
            mxB = fmaxf(mxB, fmaxf(sf[ni][2], sf[ni][3]));
        }
        mxA = fmaxf(mxA, __shfl_xor_sync(0xffffffffu, mxA, 1));
        mxA = fmaxf(mxA, __shfl_xor_sync(0xffffffffu, mxA, 2));
        mxB = fmaxf(mxB, __shfl_xor_sync(0xffffffffu, mxB, 1));
        mxB = fmaxf(mxB, __shfl_xor_sync(0xffffffffu, mxB, 2));
        float nmA = fmaxf(mA, mxA), nmB = fmaxf(mB, mxB);
        float cA = fexp(mA - nmA), cB = fexp(mB - nmB);
        float suA = 0.0f, suB = 0.0f;
#pragma unroll
        for (int ni = 0; ni < 8; ni++) {
            sf[ni][0] = fexp(sf[ni][0] - nmA);
            sf[ni][1] = fexp(sf[ni][1] - nmA);
            sf[ni][2] = fexp(sf[ni][2] - nmB);
            sf[ni][3] = fexp(sf[ni][3] - nmB);
            suA += sf[ni][0] + sf[ni][1];
            suB += sf[ni][2] + sf[ni][3];
        }
        suA += __shfl_xor_sync(0xffffffffu, suA, 1);
        suA += __shfl_xor_sync(0xffffffffu, suA, 2);
        suB += __shfl_xor_sync(0xffffffffu, suB, 1);
        suB += __shfl_xor_sync(0xffffffffu, suB, 2);
        lA = lA * cA + suA; lB = lB * cB + suB;
        mA = nmA; mB = nmB;
#pragma unroll
        for (int ni = 0; ni < 8; ni++) {
            of[ni][0] *= cA; of[ni][1] *= cA;
            of[ni][2] *= cB; of[ni][3] *= cB;
        }

        // O += P @ V : QK C-frag layout == PV A-frag layout (just pack to f16)
#pragma unroll
        for (int kc = 0; kc < 4; kc++) {
            uint32_t a[4];
            a[0] = h2pack(sf[2 * kc][0],     sf[2 * kc][1]);
            a[1] = h2pack(sf[2 * kc][2],     sf[2 * kc][3]);
            a[2] = h2pack(sf[2 * kc + 1][0], sf[2 * kc + 1][1]);
            a[3] = h2pack(sf[2 * kc + 1][2], sf[2 * kc + 1][3]);
#pragma unroll
            for (int ni = 0; ni < 8; ni++) {
                int rowB = ni * 8 + g;      // d-row of VT tile
                uint32_t b0 = ld32sw(Vsp, rowB, kc * 2,     g, q);
                uint32_t b1 = ld32sw(Vsp, rowB, kc * 2 + 1, g, q);
                mma16(of[ni], a, b0, b1);
            }
        }
        __syncthreads();   // reads of this K/V buffer done before next issue
    }

    // Epilogue -> AO [b][n][E] half
    const int bb = bh / H_, hh = bh - bb * H_;
    float iA = 1.0f / lA, iB = 1.0f / lB;
    int rA = q0 + wid * 16 + g, rB = rA + 8;
#pragma unroll
    for (int ni = 0; ni < 8; ni++) {
        int d0 = ni * 8 + 2 * q;
        uint32_t pA = h2pack(of[ni][0] * iA, of[ni][1] * iA);
        uint32_t pB = h2pack(of[ni][2] * iB, of[ni][3] * iB);
        *(uint32_t*)(O + ((size_t)(bb * N_ + rA)) * E_ + hh * D_ + d0) = pA;
        *(uint32_t*)(O + ((size_t)(bb * N_ + rB)) * E_ + hh * D_ + d0) = pB;
    }
}

// ---------------------------------------------------------------------------
extern "C" void kernel_launch(void* const* d_in, const int* in_sizes, int n_in,
                              void* d_out, int out_size)
{
    const float* x  = (const float*)d_in[0];
    const float* Wq = (const float*)d_in[1];
    const float* bq = (const float*)d_in[2];
    const float* Wk = (const float*)d_in[3];
    const float* bk = (const float*)d_in[4];
    const float* Wv = (const float*)d_in[5];
    const float* bv = (const float*)d_in[6];
    const float* Wo = (const float*)d_in[7];
    const float* bo = (const float*)d_in[8];
    float* out = (float*)d_out;

    __half *Qh, *Kh, *VTh, *AOh, *Xh, *Wh;
    cudaGetSymbolAddress((void**)&Qh,  g_Qh);
    cudaGetSymbolAddress((void**)&Kh,  g_Kh);
    cudaGetSymbolAddress((void**)&VTh, g_VTh);
    cudaGetSymbolAddress((void**)&AOh, g_AOh);
    cudaGetSymbolAddress((void**)&Xh,  g_Xh);
    cudaGetSymbolAddress((void**)&Wh,  g_Wh);

    cudaFuncSetAttribute(h_gemm<true>,
                         cudaFuncAttributeMaxDynamicSharedMemorySize, GEMM_SMEM);
    cudaFuncSetAttribute(h_gemm<false>,
                         cudaFuncAttributeMaxDynamicSharedMemorySize, GEMM_SMEM);
    cudaFuncSetAttribute(attn_h,
                         cudaFuncAttributeMaxDynamicSharedMemorySize, ATTN_SMEM);

    // Prepass: f32 -> f16 (x + 4 weights, one launch)
    {
        int total = N8X + 4 * N8W;
        to_half_kernel<<<(total + 255) / 256, 256>>>(
            (const float4*)x, (const float4*)Wq, (const float4*)Wk,
            (const float4*)Wv, (const float4*)Wo, (uint4*)Xh, (uint4*)Wh);
    }

    // Fused QKV projection (fp16 tensor cores)
    dim3 gqkv(TOK / 128, 18);
    h_gemm<true><<<gqkv, 256, GEMM_SMEM>>>(
        Xh, Wh, bq, bk, bv, Qh, Kh, VTh, nullptr);

    // Attention
    dim3 ga(N_ / 128, B_ * H_);
    attn_h<<<ga, 256, ATTN_SMEM>>>(Qh, Kh, VTh, AOh);

    // Output projection -> fp32 out
    dim3 go(TOK / 128, E_ / 128);
    h_gemm<false><<<go, 256, GEMM_SMEM>>>(
        AOh, Wh + 3 * (size_t)E_ * E_, bo, bo, bo, nullptr, nullptr, nullptr, out);
}

// round 10
// speedup vs baseline: 3.1951x; 1.0594x over previous
#include <cuda_runtime.h>
#include <cuda_fp16.h>
#include <math.h>
#include <cstdint>

#define B_   16
#define N_   1024
#define E_   768
#define H_   12
#define D_   64
#define TOK  (B_ * N_)

// Scratch (no allocations). Q,K: [b*H+h][n][d] half, Q pre-scaled 0.125.
// VT: [b*H+h][d][n] half (transposed). AO: [b][n][e] half. Xh/Wh: half inputs.
__device__ __half g_Qh [(size_t)B_ * H_ * N_ * D_];
__device__ __half g_Kh [(size_t)B_ * H_ * N_ * D_];
__device__ __half g_VTh[(size_t)B_ * H_ * N_ * D_];
__device__ __half g_AOh[(size_t)TOK * E_];
__device__ __half g_Xh [(size_t)TOK * E_];
__device__ __half g_Wh [4][(size_t)E_ * E_];

// ---------------------------------------------------------------------------
__device__ __forceinline__ uint32_t smem_u32(const void* p) {
    uint32_t a;
    asm("{ .reg .u64 t; cvta.to.shared.u64 t, %1; cvt.u32.u64 %0, t; }" : "=r"(a) : "l"(p));
    return a;
}
__device__ __forceinline__ uint32_t h2pack(float lo, float hi) {
    __half2 t = __floats2half2_rn(lo, hi);
    return *reinterpret_cast<uint32_t*>(&t);
}

// m16n8k16 fp16 mma, fp32 accumulate
__device__ __forceinline__ void mma16(float* c, const uint32_t* a,
                                      uint32_t b0, uint32_t b1) {
    asm volatile(
        "mma.sync.aligned.m16n8k16.row.col.f32.f16.f16.f32 "
        "{%0,%1,%2,%3}, {%4,%5,%6,%7}, {%8,%9}, {%0,%1,%2,%3};\n"
        : "+f"(c[0]), "+f"(c[1]), "+f"(c[2]), "+f"(c[3])
        : "r"(a[0]), "r"(a[1]), "r"(a[2]), "r"(a[3]), "r"(b0), "r"(b1));
}

// ldmatrix x4: four 8x8 b16 tiles, fragment-distributed
__device__ __forceinline__ void ldsm4(uint32_t* r, uint32_t addr) {
    asm volatile("ldmatrix.sync.aligned.m8n8.x4.shared.b16 {%0,%1,%2,%3}, [%4];"
        : "=r"(r[0]), "=r"(r[1]), "=r"(r[2]), "=r"(r[3]) : "r"(addr));
}

#define CP16(dst, src) \
    asm volatile("cp.async.cg.shared.global [%0], [%1], 16;" :: "r"(dst), "l"(src))
#define CP_COMMIT() asm volatile("cp.async.commit_group;" ::: "memory")
template <int N>
__device__ __forceinline__ void cp_wait() {
    asm volatile("cp.async.wait_group %0;" :: "n"(N) : "memory");
}

// Fast exp on the FMA pipe (no MUFU).
__device__ __forceinline__ float fexp(float x) {
    x = fmaxf(x, -80.0f);
    float t = x * 1.4426950408889634f;
    float z = t + 12582912.0f;
    int   e = __float_as_int(z);
    float f = t - (z - 12582912.0f);
    float p = 1.3333558e-3f;
    p = fmaf(p, f, 9.6181291e-3f);
    p = fmaf(p, f, 5.5504109e-2f);
    p = fmaf(p, f, 2.4022651e-1f);
    p = fmaf(p, f, 6.9314718e-1f);
    p = fmaf(p, f, 1.0f);
    return __int_as_float(__float_as_int(p) + (e << 23));
}

// ---------------------------------------------------------------------------
// Prepass: f32 -> f16 RN for x and all 4 weights in one launch. 8 elems/thread.
// ---------------------------------------------------------------------------
#define N8X (TOK * E_ / 8)
#define N8W (E_ * E_ / 8)

__global__ __launch_bounds__(256) void to_half_kernel(
    const float4* __restrict__ x,
    const float4* __restrict__ wq, const float4* __restrict__ wk,
    const float4* __restrict__ wv, const float4* __restrict__ wo,
    uint4* __restrict__ xh, uint4* __restrict__ wh)
{
    int i = blockIdx.x * blockDim.x + threadIdx.x;
    const float4* src;
    uint4* dst;
    int off;
    if (i < N8X) {
        src = x; dst = xh; off = i;
    } else {
        int j = i - N8X;
        if (j >= 4 * N8W) return;
        int w = j / N8W;
        off = j - w * N8W;
        src = (w == 0) ? wq : (w == 1) ? wk : (w == 2) ? wv : wo;
        dst = wh + (size_t)w * N8W;
    }
    float4 a = src[2 * off], b = src[2 * off + 1];
    uint4 o;
    o.x = h2pack(a.x, a.y); o.y = h2pack(a.z, a.w);
    o.z = h2pack(b.x, b.y); o.w = h2pack(b.z, b.w);
    dst[off] = o;
}

// ---------------------------------------------------------------------------
// fp16 mma GEMM: C[m,n] = A[m,:].W[n,:] + bias[n].  BM=BN=128, BK=64 halves.
// 256 thr (8 warps 4x2), warp tile 32x64. 3-stage cp.async, SW128 XOR swizzle.
// All fragment loads via ldmatrix.x4.
// ---------------------------------------------------------------------------
#define HSTG 32768                     // bytes/stage: A 16K + B 16K
#define GEMM_SMEM (3 * HSTG)           // 98304 B

template <bool QKV>
__global__ __launch_bounds__(256, 2) void h_gemm(
    const __half* __restrict__ A, const __half* __restrict__ Wbase,
    const float* __restrict__ bp0, const float* __restrict__ bp1,
    const float* __restrict__ bp2,
    __half* __restrict__ Qd, __half* __restrict__ Kd, __half* __restrict__ VTd,
    float* __restrict__ Cf)
{
    extern __shared__ char smc[];
    const uint32_t sb = smem_u32(smc);
    const int tid = threadIdx.x;
    const int wid = tid >> 5, lane = tid & 31;
    const int g = lane >> 2, q = lane & 3;
    const int wm = wid >> 1, wn = wid & 1;
    const int m0 = blockIdx.x * 128;

    int n0, which = 0;
    const __half* W;
    const float* bias;
    if (QKV) {
        which = blockIdx.y / 6;
        n0 = (blockIdx.y % 6) * 128;
        W = Wbase + (size_t)which * E_ * E_;
        bias = (which == 0) ? bp0 : (which == 1) ? bp1 : bp2;
    } else {
        n0 = blockIdx.y * 128;
        W = Wbase; bias = bp0;
    }

    auto issue = [&](int ko) {
        uint32_t base = sb + (uint32_t)(ko % 3) * HSTG;
        const __half* Ab = A + (size_t)m0 * E_ + ko * 64;
        const __half* Wb = W + (size_t)n0 * E_ + ko * 64;
#pragma unroll
        for (int i = 0; i < 4; i++) {
            int c = tid + i * 256;          // 0..1023
            int row = c >> 3, c4 = c & 7;
            uint32_t off = (uint32_t)(row * 128 + ((c4 ^ (row & 7)) << 4));
            CP16(base + off, Ab + (size_t)row * E_ + c4 * 8);
            CP16(base + 16384 + off, Wb + (size_t)row * E_ + c4 * 8);
        }
    };

    // ldmatrix per-lane constants
    const int arow = lane & 15;                 // A-row offset (within 16)
    const int aco  = lane >> 4;                 // A chunk offset
    const int brow = (lane & 7) + ((lane >> 4) << 3);   // B-row offset (within 16)
    const int bco  = (lane >> 3) & 1;                   // B chunk offset
    // row*128 bases + row&7 (A rows: base multiples of 8 -> &7 from offset only)
    uint32_t aRB[2], bRB[4];
    const int a7 = arow & 7, b7 = brow & 7;
#pragma unroll
    for (int mi = 0; mi < 2; mi++) aRB[mi] = (uint32_t)((wm * 32 + mi * 16 + arow) * 128);
#pragma unroll
    for (int p = 0; p < 4; p++)   bRB[p] = (uint32_t)((wn * 64 + p * 16 + brow) * 128 + 16384);

    float acc[2][8][4];
#pragma unroll
    for (int mi = 0; mi < 2; mi++)
#pragma unroll
        for (int ni = 0; ni < 8; ni++)
#pragma unroll
            for (int r = 0; r < 4; r++) acc[mi][ni][r] = 0.0f;

    issue(0); CP_COMMIT();
    issue(1); CP_COMMIT();

    for (int ko = 0; ko < E_ / 64; ko++) {
        if (ko + 2 < E_ / 64) issue(ko + 2);
        CP_COMMIT();
        cp_wait<2>();
        __syncthreads();
        const uint32_t st = sb + (uint32_t)(ko % 3) * HSTG;
#pragma unroll
        for (int kc = 0; kc < 4; kc++) {
            const int ck = kc * 2;
            uint32_t af[2][4];
#pragma unroll
            for (int mi = 0; mi < 2; mi++)
                ldsm4(af[mi], st + aRB[mi] + (uint32_t)(((ck + aco) ^ a7) << 4));
#pragma unroll
            for (int p = 0; p < 4; p++) {
                uint32_t bb[4];
                ldsm4(bb, st + bRB[p] + (uint32_t)(((ck + bco) ^ b7) << 4));
                mma16(acc[0][2 * p],     af[0], bb[0], bb[1]);
                mma16(acc[1][2 * p],     af[1], bb[0], bb[1]);
                mma16(acc[0][2 * p + 1], af[0], bb[2], bb[3]);
                mma16(acc[1][2 * p + 1], af[1], bb[2], bb[3]);
            }
        }
        __syncthreads();
    }

    // epilogue
#pragma unroll
    for (int mi = 0; mi < 2; mi++) {
        int r0 = m0 + wm * 32 + mi * 16 + g, r1 = r0 + 8;
#pragma unroll
        for (int ni = 0; ni < 8; ni++) {
            int cb = n0 + wn * 64 + ni * 8;
            int c0 = cb + 2 * q;
            float bx = __ldg(bias + c0), by = __ldg(bias + c0 + 1);
            float v00 = acc[mi][ni][0] + bx, v01 = acc[mi][ni][1] + by;
            float v10 = acc[mi][ni][2] + bx, v11 = acc[mi][ni][3] + by;
            if (QKV) {
                int h = cb >> 6, d0 = (cb & 63) + 2 * q;
                int bb0 = r0 >> 10, nn0 = r0 & (N_ - 1);
                int bb1 = r1 >> 10, nn1 = r1 & (N_ - 1);
                if (which == 2) {   // V: transposed [bh][d][n], scalar stores
                    size_t vbase0 = ((size_t)bb0 * H_ + h) * D_;
                    size_t vbase1 = ((size_t)bb1 * H_ + h) * D_;
                    VTd[(vbase0 + d0)     * N_ + nn0] = __float2half_rn(v00);
                    VTd[(vbase0 + d0 + 1) * N_ + nn0] = __float2half_rn(v01);
                    VTd[(vbase1 + d0)     * N_ + nn1] = __float2half_rn(v10);
                    VTd[(vbase1 + d0 + 1) * N_ + nn1] = __float2half_rn(v11);
                } else {
                    __half* C = (which == 0) ? Qd : Kd;
                    if (which == 0) { v00 *= 0.125f; v01 *= 0.125f;
                                      v10 *= 0.125f; v11 *= 0.125f; }
                    uint32_t p0 = h2pack(v00, v01), p1 = h2pack(v10, v11);
                    *(uint32_t*)(C + (((size_t)bb0 * H_ + h) * N_ + nn0) * D_ + d0) = p0;
                    *(uint32_t*)(C + (((size_t)bb1 * H_ + h) * N_ + nn1) * D_ + d0) = p1;
                }
            } else {
                *(float2*)(Cf + (size_t)r0 * E_ + c0) = make_float2(v00, v01);
                *(float2*)(Cf + (size_t)r1 * E_ + c0) = make_float2(v10, v11);
            }
        }
    }
}

// ---------------------------------------------------------------------------
// Flash attention, fp16 k16 mma + ldmatrix. Q [128][64h] @0, K 2x[64][64h]
// @16384, VT 2x[64 d][64 keys] @32768. Rows 128B, SW128 XOR swizzle.
// 8 warps, warp = 16 q-rows x 64 keys. QK C-frags ARE the PV A-frags.
// ---------------------------------------------------------------------------
#define AK_B 16384
#define AV_B 32768
#define ATTN_SMEM 49152

__global__ __launch_bounds__(256, 2) void attn_h(
    const __half* __restrict__ Q, const __half* __restrict__ K,
    const __half* __restrict__ VT, __half* __restrict__ O)
{
    extern __shared__ char smc[];
    const uint32_t sb = smem_u32(smc);
    const int tid = threadIdx.x;
    const int wid = tid >> 5, lane = tid & 31;
    const int g = lane >> 2, q = lane & 3;
    const int bh = blockIdx.y;
    const int q0 = blockIdx.x * 128;

    const __half* Qb = Q + (size_t)bh * N_ * D_ + (size_t)q0 * D_;
    const __half* Kb = K + (size_t)bh * N_ * D_;
    const __half* Vt = VT + (size_t)bh * D_ * N_;

    // Q -> smem (1024 16B chunks)
#pragma unroll
    for (int i = 0; i < 4; i++) {
        int c = tid + i * 256;
        int row = c >> 3, c4 = c & 7;
        CP16(sb + (uint32_t)(row * 128 + ((c4 ^ (row & 7)) << 4)),
             Qb + (size_t)row * D_ + c4 * 8);
    }
    CP_COMMIT();

    auto issueKV = [&](int ck) {
        uint32_t kb = sb + AK_B + (ck & 1) * 8192;
        uint32_t vb = sb + AV_B + (ck & 1) * 8192;
        const __half* Kc = Kb + (size_t)ck * 64 * D_;
        const __half* Vc = Vt + ck * 64;
#pragma unroll
        for (int i = 0; i < 2; i++) {
            int c = tid + i * 256;          // 512 chunks each
            int row = c >> 3, c4 = c & 7;
            uint32_t off = (uint32_t)(row * 128 + ((c4 ^ (row & 7)) << 4));
            CP16(kb + off, Kc + (size_t)row * D_ + c4 * 8);
            CP16(vb + off, Vc + (size_t)row * N_ + c4 * 8);
        }
    };
    issueKV(0); CP_COMMIT();

    cp_wait<1>();       // Q resident (KV0 may be in flight)
    __syncthreads();

    // ldmatrix lane constants
    const int arow = lane & 15, aco = lane >> 4;
    const int brow = (lane & 7) + ((lane >> 4) << 3);
    const int bco = (lane >> 3) & 1;
    const int a7 = arow & 7, b7 = brow & 7;
    const uint32_t qRB = (uint32_t)((wid * 16 + arow) * 128);
    uint32_t bRB[4];
#pragma unroll
    for (int p = 0; p < 4; p++) bRB[p] = (uint32_t)((p * 16 + brow) * 128);

    // Register-resident Q fragments (pre-scaled by 0.125 in gmem)
    uint32_t qf[4][4];
#pragma unroll
    for (int kc = 0; kc < 4; kc++)
        ldsm4(qf[kc], sb + qRB + (uint32_t)(((kc * 2 + aco) ^ a7) << 4));

    float of[8][4];
#pragma unroll
    for (int ni = 0; ni < 8; ni++)
#pragma unroll
        for (int r = 0; r < 4; r++) of[ni][r] = 0.0f;
    float mA = -INFINITY, mB = -INFINITY, lA = 0.0f, lB = 0.0f;

    for (int ck = 0; ck < N_ / 64; ck++) {
        if (ck + 1 < N_ / 64) issueKV(ck + 1);
        CP_COMMIT();
        cp_wait<1>();
        __syncthreads();
        const uint32_t Ksp = sb + AK_B + (ck & 1) * 8192;
        const uint32_t Vsp = sb + AV_B + (ck & 1) * 8192;

        // S = (Q/8) K^T
        float sf[8][4];
#pragma unroll
        for (int ni = 0; ni < 8; ni++)
#pragma unroll
            for (int r = 0; r < 4; r++) sf[ni][r] = 0.0f;
#pragma unroll
        for (int kc = 0; kc < 4; kc++) {
            const int ck2 = kc * 2;
#pragma unroll
            for (int p = 0; p < 4; p++) {
                uint32_t bb[4];
                ldsm4(bb, Ksp + bRB[p] + (uint32_t)(((ck2 + bco) ^ b7) << 4));
                mma16(sf[2 * p],     qf[kc], bb[0], bb[1]);
                mma16(sf[2 * p + 1], qf[kc], bb[2], bb[3]);
            }
        }

        // Online softmax (rows rA = wid*16+g, rB = rA+8)
        float mxA = -INFINITY, mxB = -INFINITY;
#pragma unroll
        for (int ni = 0; ni < 8; ni++) {
            mxA = fmaxf(mxA, fmaxf(sf[ni][0], sf[ni][1]));
            mxB = fmaxf(mxB, fmaxf(sf[ni][2], sf[ni][3]));
        }
        mxA = fmaxf(mxA, __shfl_xor_sync(0xffffffffu, mxA, 1));
        mxA = fmaxf(mxA, __shfl_xor_sync(0xffffffffu, mxA, 2));
        mxB = fmaxf(mxB, __shfl_xor_sync(0xffffffffu, mxB, 1));
        mxB = fmaxf(mxB, __shfl_xor_sync(0xffffffffu, mxB, 2));
        float nmA = fmaxf(mA, mxA), nmB = fmaxf(mB, mxB);
        float cA = fexp(mA - nmA), cB = fexp(mB - nmB);
        float suA = 0.0f, suB = 0.0f;
#pragma unroll
        for (int ni = 0; ni < 8; ni++) {
            sf[ni][0] = fexp(sf[ni][0] - nmA);
            sf[ni][1] = fexp(sf[ni][1] - nmA);
            sf[ni][2] = fexp(sf[ni][2] - nmB);
            sf[ni][3] = fexp(sf[ni][3] - nmB);
            suA += sf[ni][0] + sf[ni][1];
            suB += sf[ni][2] + sf[ni][3];
        }
        suA += __shfl_xor_sync(0xffffffffu, suA, 1);
        suA += __shfl_xor_sync(0xffffffffu, suA, 2);
        suB += __shfl_xor_sync(0xffffffffu, suB, 1);
        suB += __shfl_xor_sync(0xffffffffu, suB, 2);
        lA = lA * cA + suA; lB = lB * cB + suB;
        mA = nmA; mB = nmB;
#pragma unroll
        for (int ni = 0; ni < 8; ni++) {
            of[ni][0] *= cA; of[ni][1] *= cA;
            of[ni][2] *= cB; of[ni][3] *= cB;
        }

        // O += P @ V : QK C-frag layout == PV A-frag layout (pack to f16)
#pragma unroll
        for (int kc = 0; kc < 4; kc++) {
            uint32_t a[4];
            a[0] = h2pack(sf[2 * kc][0],     sf[2 * kc][1]);
            a[1] = h2pack(sf[2 * kc][2],     sf[2 * kc][3]);
            a[2] = h2pack(sf[2 * kc + 1][0], sf[2 * kc + 1][1]);
            a[3] = h2pack(sf[2 * kc + 1][2], sf[2 * kc + 1][3]);
            const int ck2 = kc * 2;
#pragma unroll
            for (int p = 0; p < 4; p++) {
                uint32_t bb[4];
                ldsm4(bb, Vsp + bRB[p] + (uint32_t)(((ck2 + bco) ^ b7) << 4));
                mma16(of[2 * p],     a, bb[0], bb[1]);
                mma16(of[2 * p + 1], a, bb[2], bb[3]);
            }
        }
        __syncthreads();   // reads of this K/V buffer done before next issue
    }

    // Epilogue -> AO [b][n][E] half
    const int bb = bh / H_, hh = bh - bb * H_;
    float iA = 1.0f / lA, iB = 1.0f / lB;
    int rA = q0 + wid * 16 + g, rB = rA + 8;
#pragma unroll
    for (int ni = 0; ni < 8; ni++) {
        int d0 = ni * 8 + 2 * q;
        uint32_t pA = h2pack(of[ni][0] * iA, of[ni][1] * iA);
        uint32_t pB = h2pack(of[ni][2] * iB, of[ni][3] * iB);
        *(uint32_t*)(O + ((size_t)(bb * N_ + rA)) * E_ + hh * D_ + d0) = pA;
        *(uint32_t*)(O + ((size_t)(bb * N_ + rB)) * E_ + hh * D_ + d0) = pB;
    }
}

// ---------------------------------------------------------------------------
extern "C" void kernel_launch(void* const* d_in, const int* in_sizes, int n_in,
                              void* d_out, int out_size)
{
    const float* x  = (const float*)d_in[0];
    const float* Wq = (const float*)d_in[1];
    const float* bq = (const float*)d_in[2];
    const float* Wk = (const float*)d_in[3];
    const float* bk = (const float*)d_in[4];
    const float* Wv = (const float*)d_in[5];
    const float* bv = (const float*)d_in[6];
    const float* Wo = (const float*)d_in[7];
    const float* bo = (const float*)d_in[8];
    float* out = (float*)d_out;

    __half *Qh, *Kh, *VTh, *AOh, *Xh, *Wh;
    cudaGetSymbolAddress((void**)&Qh,  g_Qh);
    cudaGetSymbolAddress((void**)&Kh,  g_Kh);
    cudaGetSymbolAddress((void**)&VTh, g_VTh);
    cudaGetSymbolAddress((void**)&AOh, g_AOh);
    cudaGetSymbolAddress((void**)&Xh,  g_Xh);
    cudaGetSymbolAddress((void**)&Wh,  g_Wh);

    cudaFuncSetAttribute(h_gemm<true>,
                         cudaFuncAttributeMaxDynamicSharedMemorySize, GEMM_SMEM);
    cudaFuncSetAttribute(h_gemm<false>,
                         cudaFuncAttributeMaxDynamicSharedMemorySize, GEMM_SMEM);
    cudaFuncSetAttribute(attn_h,
                         cudaFuncAttributeMaxDynamicSharedMemorySize, ATTN_SMEM);

    // Prepass: f32 -> f16 (x + 4 weights, one launch)
    {
        int total = N8X + 4 * N8W;
        to_half_kernel<<<(total + 255) / 256, 256>>>(
            (const float4*)x, (const float4*)Wq, (const float4*)Wk,
            (const float4*)Wv, (const float4*)Wo, (uint4*)Xh, (uint4*)Wh);
    }

    // Fused QKV projection (fp16 tensor cores)
    dim3 gqkv(TOK / 128, 18);
    h_gemm<true><<<gqkv, 256, GEMM_SMEM>>>(
        Xh, Wh, bq, bk, bv, Qh, Kh, VTh, nullptr);

    // Attention
    dim3 ga(N_ / 128, B_ * H_);
    attn_h<<<ga, 256, ATTN_SMEM>>>(Qh, Kh, VTh, AOh);

    // Output projection -> fp32 out
    dim3 go(TOK / 128, E_ / 128);
    h_gemm<false><<<go, 256, GEMM_SMEM>>>(
        AOh, Wh + 3 * (size_t)E_ * E_, bo, bo, bo, nullptr, nullptr, nullptr, out);
}